// round 7
// baseline (speedup 1.0000x reference)
#include <cuda_runtime.h>
#include <cuda_bf16.h>
#include <cstdint>

// ---------------------------------------------------------------------------
// DeepFM: out = bias + first + second + MLP(emb)
// INT8 IMMA GEMMs (m16n8k32 s8), CTA 128x128, BK=64, NS=4, 256 thr (R4-best).
// Dense-emb slice excluded from int8 GEMM (scale mismatch); its exact
// contribution dense @ (Wd@W1[0:64]) is added in G1's epilogue via Wproj.
// Scales: emb/h1/W = x1024, h2 = x2048. FM terms exact fp32.
// G3 fuses h3 @ Wout into epilogue (atomicAdd into out).
// ---------------------------------------------------------------------------

namespace cfg {
constexpr int B  = 16384;
constexpr int F  = 26;
constexpr int V  = 100000;
constexpr int D  = 64;
constexpr int ND = 13;
constexpr int H1 = 1024;
constexpr int H2 = 512;
constexpr int H3 = 256;
constexpr int KS = F * D;        // 1664 (sparse-only K for G1)
}

constexpr float SW    = 1024.f;                 // weight scale
constexpr float SA1   = 1024.f;                 // emb scale
constexpr float SH1   = 1024.f;                 // h1 scale
constexpr float SH2   = 2048.f;                 // h2 scale
constexpr float INV1  = 1.f / (1024.f * 1024.f);   // G1 acc -> true
constexpr float QK2   = 2048.f / (1024.f * 1024.f);// G2 acc -> h2 counts
constexpr float INV3  = 1.f / (2048.f * 1024.f);   // G3 acc -> true

// ------------------------- scratch (device globals) ------------------------
__device__ int8_t g_h  [(size_t)cfg::B * cfg::KS];   // sparse emb, x1024
__device__ int8_t g_h1 [(size_t)cfg::B * cfg::H1];   // x1024
__device__ int8_t g_h2 [(size_t)cfg::B * cfg::H2];   // x2048
__device__ int8_t g_Wt1[cfg::H1 * cfg::KS];          // [N,K] s8, x1024
__device__ int8_t g_Wt2[cfg::H2 * cfg::H1];
__device__ int8_t g_Wt3[cfg::H3 * cfg::H2];
__device__ float  g_Wp [cfg::ND * cfg::H1];          // Wd @ W1[0:64] (fp32)

__device__ __forceinline__ int8_t to_s8(float v) {
    return (int8_t)__float2int_rn(fminf(fmaxf(v, -127.f), 127.f));
}

// ------------------------- Wproj = Wd @ W1[0:64,:] -------------------------
__global__ __launch_bounds__(256) void wproj_kernel(
    const float* __restrict__ Wd, const float* __restrict__ W1) {
    int n = blockIdx.x * blockDim.x + threadIdx.x;
    if (n >= cfg::H1) return;
#pragma unroll
    for (int i = 0; i < cfg::ND; i++) {
        float s = 0.f;
#pragma unroll
        for (int d = 0; d < cfg::D; d++)
            s += Wd[i * cfg::D + d] * W1[(size_t)d * cfg::H1 + n];
        g_Wp[i * cfg::H1 + n] = s;
    }
}

// ------------------------- weight transpose+convert ------------------------
// out[n*K + k] = s8(in[k*N + n] * 1024)
__global__ __launch_bounds__(256) void transpose_convert(
    const float* __restrict__ in, int8_t* __restrict__ out, int K, int N) {
    __shared__ float t[32][33];
    const int tx = threadIdx.x & 31, ty = threadIdx.x >> 5;  // 32x8
    const int n0 = blockIdx.x * 32, k0 = blockIdx.y * 32;
#pragma unroll
    for (int j = 0; j < 4; j++)
        t[ty + j * 8][tx] = in[(size_t)(k0 + ty + j * 8) * N + n0 + tx];
    __syncthreads();
#pragma unroll
    for (int j = 0; j < 4; j++)
        out[(size_t)(n0 + ty + j * 8) * K + k0 + tx] =
            to_s8(t[tx][ty + j * 8] * SW);
}

// ------------------------- embed + FM (fp32 exact) -------------------------
__global__ __launch_bounds__(256) void embed_kernel(
    const float* __restrict__ dense, const int* __restrict__ sidx,
    const float* __restrict__ bias, const float* __restrict__ emb_tables,
    const float* __restrict__ lin_tables, const float* __restrict__ Wd,
    const float* __restrict__ Wld, const float* __restrict__ bld,
    float* __restrict__ out) {
    const int sub = threadIdx.x >> 6;
    const int d   = threadIdx.x & 63;
    const int row = blockIdx.x * 4 + sub;

    const float* dr = dense + (size_t)row * cfg::ND;

    int idx[cfg::F];
#pragma unroll
    for (int f = 0; f < cfg::F; f++) idx[f] = __ldg(sidx + (size_t)row * cfg::F + f);

    float ev[cfg::F];
#pragma unroll
    for (int f = 0; f < cfg::F; f++)
        ev[f] = __ldg(emb_tables + ((size_t)f * cfg::V + idx[f]) * cfg::D + d);

    float lin = 0.f;
    if (d < cfg::F) lin = __ldg(lin_tables + (size_t)d * cfg::V + idx[d]);

    float de = 0.f;
#pragma unroll
    for (int i = 0; i < cfg::ND; i++) de += dr[i] * Wd[i * cfg::D + d];

    float s  = de;
    float sq = de * de;
    int8_t* hrow = g_h + (size_t)row * cfg::KS;

#pragma unroll
    for (int f = 0; f < cfg::F; f++) {
        float e = ev[f];
        s  += e;
        sq += e * e;
        hrow[f * cfg::D + d] = to_s8(e * SA1);   // sparse slices only
    }

    float val = 0.5f * (s * s - sq) + lin;
    if (d < cfg::ND) val += dr[d] * Wld[d];

#pragma unroll
    for (int o = 16; o > 0; o >>= 1)
        val += __shfl_down_sync(0xffffffffu, val, o);

    __shared__ float red[8];
    if ((threadIdx.x & 31) == 0) red[threadIdx.x >> 5] = val;
    __syncthreads();
    if (d == 0)
        out[row] = bias[0] + bld[0] + red[sub * 2] + red[sub * 2 + 1];
}

// ------------------------- INT8 tensor-core GEMM ---------------------------
// CTA 128x128, 8 warps (4M x 2N), warp tile 32x64, BK=64, NS=4 stages.
#define BM 128
#define BN 128
#define BK 64
#define NS 4
#define TSTR 80                     // 64B row + 16B pad (conflict-free)
#define A_ST (BM * TSTR)            // 10240 B / stage
#define B_ST (BN * TSTR)            // 10240 B / stage
#define STAGE_B (A_ST + B_ST)
#define GEMM_SMEM (NS * STAGE_B)    // 81920 B

__device__ __forceinline__ uint32_t smem_u32(const void* p) {
    return (uint32_t)__cvta_generic_to_shared(p);
}
__device__ __forceinline__ void cp16(uint32_t s, const void* g) {
    asm volatile("cp.async.cg.shared.global [%0], [%1], 16;\n" ::"r"(s), "l"(g));
}
__device__ __forceinline__ void cp_commit() {
    asm volatile("cp.async.commit_group;\n");
}
template <int N> __device__ __forceinline__ void cp_wait() {
    asm volatile("cp.async.wait_group %0;\n" ::"n"(N));
}
__device__ __forceinline__ void ldm_x4(uint32_t a, uint32_t& r0, uint32_t& r1,
                                       uint32_t& r2, uint32_t& r3) {
    asm volatile("ldmatrix.sync.aligned.m8n8.x4.shared.b16 {%0,%1,%2,%3}, [%4];\n"
                 : "=r"(r0), "=r"(r1), "=r"(r2), "=r"(r3)
                 : "r"(a));
}
__device__ __forceinline__ void mma_s8(int* c, const uint32_t* a,
                                       uint32_t b0, uint32_t b1) {
    asm volatile(
        "mma.sync.aligned.m16n8k32.row.col.s32.s8.s8.s32 "
        "{%0,%1,%2,%3}, {%4,%5,%6,%7}, {%8,%9}, {%0,%1,%2,%3};\n"
        : "+r"(c[0]), "+r"(c[1]), "+r"(c[2]), "+r"(c[3])
        : "r"(a[0]), "r"(a[1]), "r"(a[2]), "r"(a[3]), "r"(b0), "r"(b1));
}

// MODE 0: C = s8(relu(acc)*qk)                    (G2)
// MODE 1: C = s8(relu(acc*INV1 + dense@Wp)*SH1)   (G1, dense fold)
// MODE 2: out[m] += relu(acc)@Wout * INV3         (G3, Wout fold)
template <int MODE>
__global__ __launch_bounds__(256, 2) void gemm_s8(
    const int8_t* __restrict__ A, const int8_t* __restrict__ Wt,
    int8_t* __restrict__ C, const float* __restrict__ dense,
    const float* __restrict__ Wout, float* __restrict__ out,
    float qk, int M, int N, int K)
{
    extern __shared__ __align__(16) uint8_t smem[];

    const int tid  = threadIdx.x;
    const int bm   = blockIdx.y * BM;
    const int bn   = blockIdx.x * BN;
    const int wid  = tid >> 5;
    const int lane = tid & 31;
    const int wm   = (wid & 3) * 32;   // 4 warps over M
    const int wn   = (wid >> 2) * 64;  // 2 warps over N

    auto load_tiles = [&](int buf, int kofs) {
        uint8_t* sA = smem + buf * STAGE_B;
        uint8_t* sB = sA + A_ST;
#pragma unroll
        for (int it = 0; it < 2; it++) {          // A: 512 x 16B
            int c = tid + it * 256;
            int r = c >> 2, cg = c & 3;
            cp16(smem_u32(sA + r * TSTR + cg * 16),
                 A + (size_t)(bm + r) * K + kofs + cg * 16);
        }
#pragma unroll
        for (int it = 0; it < 2; it++) {          // B: 512 x 16B
            int c = tid + it * 256;
            int r = c >> 2, cg = c & 3;
            cp16(smem_u32(sB + r * TSTR + cg * 16),
                 Wt + (size_t)(bn + r) * K + kofs + cg * 16);
        }
    };

    int acc[2][8][4];
#pragma unroll
    for (int i = 0; i < 2; i++)
#pragma unroll
        for (int j = 0; j < 8; j++)
#pragma unroll
            for (int k = 0; k < 4; k++) acc[i][j][k] = 0;

    const int KT = K / BK;

#pragma unroll
    for (int s = 0; s < NS - 1; s++) {
        load_tiles(s, s * BK);
        cp_commit();
    }

    for (int kt = 0; kt < KT; kt++) {
        const int buf = kt % NS;
        cp_wait<NS - 2>();
        __syncthreads();

        const int pf = kt + NS - 1;
        if (pf < KT) load_tiles(pf % NS, pf * BK);
        cp_commit();

        uint8_t* sA = smem + buf * STAGE_B;
        uint8_t* sB = sA + A_ST;
#pragma unroll
        for (int ks = 0; ks < 2; ks++) {         // two k32 steps
            uint32_t af[2][4];
#pragma unroll
            for (int mi = 0; mi < 2; mi++) {
                int r = wm + mi * 16 + (lane & 15);
                int cb = ks * 32 + (lane >> 4) * 16;
                ldm_x4(smem_u32(sA + r * TSTR + cb),
                       af[mi][0], af[mi][1], af[mi][2], af[mi][3]);
            }
            uint32_t bf[4][4];
#pragma unroll
            for (int nj = 0; nj < 4; nj++) {
                int r = wn + nj * 16 + (lane & 15);
                int cb = ks * 32 + (lane >> 4) * 16;
                ldm_x4(smem_u32(sB + r * TSTR + cb),
                       bf[nj][0], bf[nj][1], bf[nj][2], bf[nj][3]);
            }
#pragma unroll
            for (int mi = 0; mi < 2; mi++)
#pragma unroll
                for (int nj = 0; nj < 4; nj++) {
                    mma_s8(acc[mi][nj * 2],     af[mi], bf[nj][0], bf[nj][2]);
                    mma_s8(acc[mi][nj * 2 + 1], af[mi], bf[nj][1], bf[nj][3]);
                }
        }
    }

    const int lr = lane >> 2, lc = (lane & 3) * 2;

    if (MODE == 1) {
        // repurpose stage smem for the Wp slice [13 x BN] fp32
        __syncthreads();
        float* swp = reinterpret_cast<float*>(smem);
        for (int i = tid; i < cfg::ND * BN; i += 256)
            swp[i] = __ldg(g_Wp + (i / BN) * cfg::H1 + bn + (i % BN));
        __syncthreads();
#pragma unroll
        for (int mi = 0; mi < 2; mi++)
#pragma unroll
            for (int half = 0; half < 2; half++) {
                int m = bm + wm + mi * 16 + lr + half * 8;
                const float* drow = dense + (size_t)m * cfg::ND;
                float add[16];
#pragma unroll
                for (int q = 0; q < 16; q++) add[q] = 0.f;
#pragma unroll
                for (int i = 0; i < cfg::ND; i++) {
                    float dv = __ldg(drow + i);
                    const float* wrow = swp + i * BN + wn;
#pragma unroll
                    for (int ni = 0; ni < 8; ni++) {
                        add[ni * 2]     += dv * wrow[ni * 8 + lc];
                        add[ni * 2 + 1] += dv * wrow[ni * 8 + lc + 1];
                    }
                }
#pragma unroll
                for (int ni = 0; ni < 8; ni++) {
                    float x0 = (float)acc[mi][ni][half * 2]     * INV1 + add[ni * 2];
                    float x1 = (float)acc[mi][ni][half * 2 + 1] * INV1 + add[ni * 2 + 1];
                    int8_t q0 = to_s8(fmaxf(x0, 0.f) * SH1);
                    int8_t q1 = to_s8(fmaxf(x1, 0.f) * SH1);
                    int n0 = bn + wn + ni * 8 + lc;
                    *reinterpret_cast<short*>(C + (size_t)m * N + n0) =
                        (short)((uint8_t)q0 | ((uint8_t)q1 << 8));
                }
            }
    } else if (MODE == 2) {
#pragma unroll
        for (int mi = 0; mi < 2; mi++) {
            float s0 = 0.f, s1 = 0.f;
#pragma unroll
            for (int ni = 0; ni < 8; ni++) {
                int n0 = bn + wn + ni * 8 + lc;
                float w0 = __ldg(Wout + n0);
                float w1 = __ldg(Wout + n0 + 1);
                s0 += (float)max(acc[mi][ni][0], 0) * w0 +
                      (float)max(acc[mi][ni][1], 0) * w1;
                s1 += (float)max(acc[mi][ni][2], 0) * w0 +
                      (float)max(acc[mi][ni][3], 0) * w1;
            }
            s0 += __shfl_xor_sync(0xffffffffu, s0, 1);
            s0 += __shfl_xor_sync(0xffffffffu, s0, 2);
            s1 += __shfl_xor_sync(0xffffffffu, s1, 1);
            s1 += __shfl_xor_sync(0xffffffffu, s1, 2);
            if ((lane & 3) == 0) {
                int m0 = bm + wm + mi * 16 + lr;
                atomicAdd(out + m0,     s0 * INV3);
                atomicAdd(out + m0 + 8, s1 * INV3);
            }
        }
    } else {
#pragma unroll
        for (int mi = 0; mi < 2; mi++)
#pragma unroll
            for (int ni = 0; ni < 8; ni++) {
                int m0 = bm + wm + mi * 16 + lr;
                int n0 = bn + wn + ni * 8 + lc;
                int8_t q0 = to_s8((float)max(acc[mi][ni][0], 0) * qk);
                int8_t q1 = to_s8((float)max(acc[mi][ni][1], 0) * qk);
                int8_t q2 = to_s8((float)max(acc[mi][ni][2], 0) * qk);
                int8_t q3 = to_s8((float)max(acc[mi][ni][3], 0) * qk);
                *reinterpret_cast<short*>(C + (size_t)m0 * N + n0) =
                    (short)((uint8_t)q0 | ((uint8_t)q1 << 8));
                *reinterpret_cast<short*>(C + (size_t)(m0 + 8) * N + n0) =
                    (short)((uint8_t)q2 | ((uint8_t)q3 << 8));
            }
    }
}

// ------------------------- launch ------------------------------------------
extern "C" void kernel_launch(void* const* d_in, const int* in_sizes, int n_in,
                              void* d_out, int out_size) {
    const float* dense = (const float*)d_in[0];
    const int*   sidx  = (const int*)d_in[1];
    const float* bias  = (const float*)d_in[2];
    const float* emb   = (const float*)d_in[3];
    const float* lin   = (const float*)d_in[4];
    const float* Wd    = (const float*)d_in[5];
    const float* Wld   = (const float*)d_in[6];
    const float* bld   = (const float*)d_in[7];
    const float* W1    = (const float*)d_in[8];
    const float* W2    = (const float*)d_in[9];
    const float* W3    = (const float*)d_in[10];
    const float* Wout  = (const float*)d_in[11];
    float* out = (float*)d_out;

    void *p_h, *p_h1, *p_h2, *p_W1, *p_W2, *p_W3;
    cudaGetSymbolAddress(&p_h,  g_h);
    cudaGetSymbolAddress(&p_h1, g_h1);
    cudaGetSymbolAddress(&p_h2, g_h2);
    cudaGetSymbolAddress(&p_W1, g_Wt1);
    cudaGetSymbolAddress(&p_W2, g_Wt2);
    cudaGetSymbolAddress(&p_W3, g_Wt3);

    static bool attr_done = false;
    if (!attr_done) {
        cudaFuncSetAttribute(gemm_s8<0>,
                             cudaFuncAttributeMaxDynamicSharedMemorySize, GEMM_SMEM);
        cudaFuncSetAttribute(gemm_s8<1>,
                             cudaFuncAttributeMaxDynamicSharedMemorySize, GEMM_SMEM);
        cudaFuncSetAttribute(gemm_s8<2>,
                             cudaFuncAttributeMaxDynamicSharedMemorySize, GEMM_SMEM);
        attr_done = true;
    }

    wproj_kernel<<<cfg::H1 / 256, 256>>>(Wd, W1);
    // W1 sparse rows only (skip first 64 = dense slice)
    transpose_convert<<<dim3(cfg::H1 / 32, cfg::KS / 32), 256>>>(
        W1 + (size_t)cfg::D * cfg::H1, (int8_t*)p_W1, cfg::KS, cfg::H1);
    transpose_convert<<<dim3(cfg::H2 / 32, cfg::H1 / 32), 256>>>(
        W2, (int8_t*)p_W2, cfg::H1, cfg::H2);
    transpose_convert<<<dim3(cfg::H3 / 32, cfg::H2 / 32), 256>>>(
        W3, (int8_t*)p_W3, cfg::H2, cfg::H3);

    embed_kernel<<<cfg::B / 4, 256>>>(dense, sidx, bias, emb, lin, Wd, Wld,
                                      bld, out);

    dim3 g1(cfg::H1 / BN, cfg::B / BM);
    gemm_s8<1><<<g1, 256, GEMM_SMEM>>>(
        (const int8_t*)p_h, (const int8_t*)p_W1, (int8_t*)p_h1,
        dense, nullptr, nullptr, 0.f, cfg::B, cfg::H1, cfg::KS);
    dim3 g2(cfg::H2 / BN, cfg::B / BM);
    gemm_s8<0><<<g2, 256, GEMM_SMEM>>>(
        (const int8_t*)p_h1, (const int8_t*)p_W2, (int8_t*)p_h2,
        nullptr, nullptr, nullptr, QK2, cfg::B, cfg::H2, cfg::H1);
    dim3 g3(cfg::H3 / BN, cfg::B / BM);
    gemm_s8<2><<<g3, 256, GEMM_SMEM>>>(
        (const int8_t*)p_h2, (const int8_t*)p_W3, nullptr,
        nullptr, Wout, out, 0.f, cfg::B, cfg::H3, cfg::H2);
}

// round 8
// speedup vs baseline: 1.9752x; 1.9752x over previous
#include <cuda_runtime.h>
#include <cuda_fp16.h>
#include <cstdint>

// ---------------------------------------------------------------------------
// DeepFM: out = bias + first + second + MLP(emb)
// FP16 HMMA GEMMs with FP16 accumulators (m16n8k16 f16.f16.f16.f16),
// CTA 128x128, BK=32 (64B k-chunks), NS=4 cp.async, 256 threads.
// No scaling needed: all values in natural units (fp16 range is ample).
// G3 fuses h3 @ Wout into epilogue (atomicAdd into out). FM terms exact fp32.
// ---------------------------------------------------------------------------

namespace cfg {
constexpr int B  = 16384;
constexpr int F  = 26;
constexpr int V  = 100000;
constexpr int D  = 64;
constexpr int ND = 13;
constexpr int H1 = 1024;
constexpr int H2 = 512;
constexpr int H3 = 256;
constexpr int K0 = (F + 1) * D;  // 1728
}

// ------------------------- scratch (device globals) ------------------------
__device__ __half g_h  [(size_t)cfg::B * cfg::K0];
__device__ __half g_h1 [(size_t)cfg::B * cfg::H1];
__device__ __half g_h2 [(size_t)cfg::B * cfg::H2];
__device__ __half g_Wt1[cfg::H1 * cfg::K0];          // [N,K] fp16
__device__ __half g_Wt2[cfg::H2 * cfg::H1];
__device__ __half g_Wt3[cfg::H3 * cfg::H2];

// ------------------------- weight transpose+convert ------------------------
// out[n*K + k] = fp16(in[k*N + n])
__global__ __launch_bounds__(256) void transpose_convert(
    const float* __restrict__ in, __half* __restrict__ out, int K, int N) {
    __shared__ float t[32][33];
    const int tx = threadIdx.x & 31, ty = threadIdx.x >> 5;  // 32x8
    const int n0 = blockIdx.x * 32, k0 = blockIdx.y * 32;
#pragma unroll
    for (int j = 0; j < 4; j++)
        t[ty + j * 8][tx] = in[(size_t)(k0 + ty + j * 8) * N + n0 + tx];
    __syncthreads();
#pragma unroll
    for (int j = 0; j < 4; j++)
        out[(size_t)(n0 + ty + j * 8) * K + k0 + tx] =
            __float2half(t[tx][ty + j * 8]);
}

// ------------------------- embed + FM (fp32 exact) -------------------------
__global__ __launch_bounds__(256) void embed_kernel(
    const float* __restrict__ dense, const int* __restrict__ sidx,
    const float* __restrict__ bias, const float* __restrict__ emb_tables,
    const float* __restrict__ lin_tables, const float* __restrict__ Wd,
    const float* __restrict__ Wld, const float* __restrict__ bld,
    float* __restrict__ out) {
    const int sub = threadIdx.x >> 6;
    const int d   = threadIdx.x & 63;
    const int row = blockIdx.x * 4 + sub;

    const float* dr = dense + (size_t)row * cfg::ND;

    int idx[cfg::F];
#pragma unroll
    for (int f = 0; f < cfg::F; f++) idx[f] = __ldg(sidx + (size_t)row * cfg::F + f);

    float ev[cfg::F];
#pragma unroll
    for (int f = 0; f < cfg::F; f++)
        ev[f] = __ldg(emb_tables + ((size_t)f * cfg::V + idx[f]) * cfg::D + d);

    float lin = 0.f;
    if (d < cfg::F) lin = __ldg(lin_tables + (size_t)d * cfg::V + idx[d]);

    float de = 0.f;
#pragma unroll
    for (int i = 0; i < cfg::ND; i++) de += dr[i] * Wd[i * cfg::D + d];

    float s  = de;
    float sq = de * de;
    __half* hrow = g_h + (size_t)row * cfg::K0;
    hrow[d] = __float2half(de);

#pragma unroll
    for (int f = 0; f < cfg::F; f++) {
        float e = ev[f];
        s  += e;
        sq += e * e;
        hrow[(size_t)(f + 1) * cfg::D + d] = __float2half(e);
    }

    float val = 0.5f * (s * s - sq) + lin;
    if (d < cfg::ND) val += dr[d] * Wld[d];

#pragma unroll
    for (int o = 16; o > 0; o >>= 1)
        val += __shfl_down_sync(0xffffffffu, val, o);

    __shared__ float red[8];
    if ((threadIdx.x & 31) == 0) red[threadIdx.x >> 5] = val;
    __syncthreads();
    if (d == 0)
        out[row] = bias[0] + bld[0] + red[sub * 2] + red[sub * 2 + 1];
}

// ------------------------- FP16 tensor-core GEMM ---------------------------
// CTA 128x128, 8 warps (4M x 2N), warp tile 32x64, BK=32 fp16 (64B), NS=4.
#define BM 128
#define BN 128
#define BK 32
#define NS 4
#define TSTR 80                     // 64B row + 16B pad (conflict-free)
#define A_ST (BM * TSTR)            // 10240 B / stage
#define B_ST (BN * TSTR)            // 10240 B / stage
#define STAGE_B (A_ST + B_ST)
#define GEMM_SMEM (NS * STAGE_B)    // 81920 B

__device__ __forceinline__ uint32_t smem_u32(const void* p) {
    return (uint32_t)__cvta_generic_to_shared(p);
}
__device__ __forceinline__ void cp16(uint32_t s, const void* g) {
    asm volatile("cp.async.cg.shared.global [%0], [%1], 16;\n" ::"r"(s), "l"(g));
}
__device__ __forceinline__ void cp_commit() {
    asm volatile("cp.async.commit_group;\n");
}
template <int N> __device__ __forceinline__ void cp_wait() {
    asm volatile("cp.async.wait_group %0;\n" ::"n"(N));
}
__device__ __forceinline__ void ldm_x4(uint32_t a, uint32_t& r0, uint32_t& r1,
                                       uint32_t& r2, uint32_t& r3) {
    asm volatile("ldmatrix.sync.aligned.m8n8.x4.shared.b16 {%0,%1,%2,%3}, [%4];\n"
                 : "=r"(r0), "=r"(r1), "=r"(r2), "=r"(r3)
                 : "r"(a));
}
// f16 accumulate: D,C are 2 regs (4 halves)
__device__ __forceinline__ void mma_f16(uint32_t* c, const uint32_t* a,
                                        uint32_t b0, uint32_t b1) {
    asm volatile(
        "mma.sync.aligned.m16n8k16.row.col.f16.f16.f16.f16 "
        "{%0,%1}, {%2,%3,%4,%5}, {%6,%7}, {%0,%1};\n"
        : "+r"(c[0]), "+r"(c[1])
        : "r"(a[0]), "r"(a[1]), "r"(a[2]), "r"(a[3]), "r"(b0), "r"(b1));
}

// MODE 0: C = relu(acc) fp16.   MODE 1: out[m] += relu(acc) @ Wout.
template <int MODE>
__global__ __launch_bounds__(256, 2) void gemm_f16(
    const __half* __restrict__ A, const __half* __restrict__ Wt,
    __half* __restrict__ C, const float* __restrict__ Wout,
    float* __restrict__ out, int M, int N, int K)
{
    extern __shared__ __align__(16) uint8_t smem[];

    const int tid  = threadIdx.x;
    const int bm   = blockIdx.y * BM;
    const int bn   = blockIdx.x * BN;
    const int wid  = tid >> 5;
    const int lane = tid & 31;
    const int wm   = (wid & 3) * 32;   // 4 warps over M
    const int wn   = (wid >> 2) * 64;  // 2 warps over N

    auto load_tiles = [&](int buf, int kofs) {
        uint8_t* sA = smem + buf * STAGE_B;
        uint8_t* sB = sA + A_ST;
#pragma unroll
        for (int it = 0; it < 2; it++) {          // A: 128 rows x 4 x 16B
            int c = tid + it * 256;
            int r = c >> 2, cg = c & 3;
            cp16(smem_u32(sA + r * TSTR + cg * 16),
                 A + (size_t)(bm + r) * K + kofs + cg * 8);
        }
#pragma unroll
        for (int it = 0; it < 2; it++) {          // B: 128 n-rows x 4 x 16B
            int c = tid + it * 256;
            int r = c >> 2, cg = c & 3;
            cp16(smem_u32(sB + r * TSTR + cg * 16),
                 Wt + (size_t)(bn + r) * K + kofs + cg * 8);
        }
    };

    uint32_t acc[2][8][2];   // f16x2 accumulators
#pragma unroll
    for (int i = 0; i < 2; i++)
#pragma unroll
        for (int j = 0; j < 8; j++) {
            acc[i][j][0] = 0u;
            acc[i][j][1] = 0u;
        }

    const int KT = K / BK;

#pragma unroll
    for (int s = 0; s < NS - 1; s++) {
        load_tiles(s, s * BK);
        cp_commit();
    }

    for (int kt = 0; kt < KT; kt++) {
        const int buf = kt % NS;
        cp_wait<NS - 2>();
        __syncthreads();

        const int pf = kt + NS - 1;
        if (pf < KT) load_tiles(pf % NS, pf * BK);
        cp_commit();

        uint8_t* sA = smem + buf * STAGE_B;
        uint8_t* sB = sA + A_ST;
#pragma unroll
        for (int ks = 0; ks < 2; ks++) {         // two k16 steps
            uint32_t af[2][4];
#pragma unroll
            for (int mi = 0; mi < 2; mi++) {
                int r = wm + mi * 16 + (lane & 15);
                int cb = ks * 32 + (lane >> 4) * 16;   // bytes
                ldm_x4(smem_u32(sA + r * TSTR + cb),
                       af[mi][0], af[mi][1], af[mi][2], af[mi][3]);
            }
            uint32_t bf[4][4];
#pragma unroll
            for (int nj = 0; nj < 4; nj++) {
                int r = wn + nj * 16 + (lane & 15);
                int cb = ks * 32 + (lane >> 4) * 16;
                ldm_x4(smem_u32(sB + r * TSTR + cb),
                       bf[nj][0], bf[nj][1], bf[nj][2], bf[nj][3]);
            }
            // bf regs: r0 n(0-7)k(0-7), r1 n(8-15)k(0-7),
            //          r2 n(0-7)k(8-15), r3 n(8-15)k(8-15)
#pragma unroll
            for (int mi = 0; mi < 2; mi++)
#pragma unroll
                for (int nj = 0; nj < 4; nj++) {
                    mma_f16(acc[mi][nj * 2],     af[mi], bf[nj][0], bf[nj][2]);
                    mma_f16(acc[mi][nj * 2 + 1], af[mi], bf[nj][1], bf[nj][3]);
                }
        }
    }

    const int lr = lane >> 2, lc = (lane & 3) * 2;
    if (MODE == 1) {
        // out[m] += relu(acc) @ Wout
#pragma unroll
        for (int mi = 0; mi < 2; mi++) {
            float s0 = 0.f, s1 = 0.f;
#pragma unroll
            for (int ni = 0; ni < 8; ni++) {
                int n0 = bn + wn + ni * 8 + lc;
                float w0 = __ldg(Wout + n0);
                float w1 = __ldg(Wout + n0 + 1);
                float2 f0 = __half22float2(
                    *reinterpret_cast<__half2*>(&acc[mi][ni][0]));
                float2 f1 = __half22float2(
                    *reinterpret_cast<__half2*>(&acc[mi][ni][1]));
                s0 += fmaxf(f0.x, 0.f) * w0 + fmaxf(f0.y, 0.f) * w1;
                s1 += fmaxf(f1.x, 0.f) * w0 + fmaxf(f1.y, 0.f) * w1;
            }
            s0 += __shfl_xor_sync(0xffffffffu, s0, 1);
            s0 += __shfl_xor_sync(0xffffffffu, s0, 2);
            s1 += __shfl_xor_sync(0xffffffffu, s1, 1);
            s1 += __shfl_xor_sync(0xffffffffu, s1, 2);
            if ((lane & 3) == 0) {
                int m0 = bm + wm + mi * 16 + lr;
                atomicAdd(out + m0,     s0);
                atomicAdd(out + m0 + 8, s1);
            }
        }
    } else {
        const __half2 z2 = __float2half2_rn(0.f);
#pragma unroll
        for (int mi = 0; mi < 2; mi++)
#pragma unroll
            for (int ni = 0; ni < 8; ni++) {
                int m0 = bm + wm + mi * 16 + lr;
                int n0 = bn + wn + ni * 8 + lc;
                __half2 v0 = __hmax2(
                    *reinterpret_cast<__half2*>(&acc[mi][ni][0]), z2);
                __half2 v1 = __hmax2(
                    *reinterpret_cast<__half2*>(&acc[mi][ni][1]), z2);
                *reinterpret_cast<__half2*>(C + (size_t)m0 * N + n0) = v0;
                *reinterpret_cast<__half2*>(C + (size_t)(m0 + 8) * N + n0) = v1;
            }
    }
}

// ------------------------- launch ------------------------------------------
extern "C" void kernel_launch(void* const* d_in, const int* in_sizes, int n_in,
                              void* d_out, int out_size) {
    const float* dense = (const float*)d_in[0];
    const int*   sidx  = (const int*)d_in[1];
    const float* bias  = (const float*)d_in[2];
    const float* emb   = (const float*)d_in[3];
    const float* lin   = (const float*)d_in[4];
    const float* Wd    = (const float*)d_in[5];
    const float* Wld   = (const float*)d_in[6];
    const float* bld   = (const float*)d_in[7];
    const float* W1    = (const float*)d_in[8];
    const float* W2    = (const float*)d_in[9];
    const float* W3    = (const float*)d_in[10];
    const float* Wout  = (const float*)d_in[11];
    float* out = (float*)d_out;

    void *p_h, *p_h1, *p_h2, *p_W1, *p_W2, *p_W3;
    cudaGetSymbolAddress(&p_h,  g_h);
    cudaGetSymbolAddress(&p_h1, g_h1);
    cudaGetSymbolAddress(&p_h2, g_h2);
    cudaGetSymbolAddress(&p_W1, g_Wt1);
    cudaGetSymbolAddress(&p_W2, g_Wt2);
    cudaGetSymbolAddress(&p_W3, g_Wt3);

    static bool attr_done = false;
    if (!attr_done) {
        cudaFuncSetAttribute(gemm_f16<0>,
                             cudaFuncAttributeMaxDynamicSharedMemorySize, GEMM_SMEM);
        cudaFuncSetAttribute(gemm_f16<1>,
                             cudaFuncAttributeMaxDynamicSharedMemorySize, GEMM_SMEM);
        attr_done = true;
    }

    transpose_convert<<<dim3(cfg::H1 / 32, cfg::K0 / 32), 256>>>(
        W1, (__half*)p_W1, cfg::K0, cfg::H1);
    transpose_convert<<<dim3(cfg::H2 / 32, cfg::H1 / 32), 256>>>(
        W2, (__half*)p_W2, cfg::H1, cfg::H2);
    transpose_convert<<<dim3(cfg::H3 / 32, cfg::H2 / 32), 256>>>(
        W3, (__half*)p_W3, cfg::H2, cfg::H3);

    embed_kernel<<<cfg::B / 4, 256>>>(dense, sidx, bias, emb, lin, Wd, Wld,
                                      bld, out);

    dim3 g1(cfg::H1 / BN, cfg::B / BM);
    gemm_f16<0><<<g1, 256, GEMM_SMEM>>>(
        (const __half*)p_h, (const __half*)p_W1, (__half*)p_h1,
        nullptr, nullptr, cfg::B, cfg::H1, cfg::K0);
    dim3 g2(cfg::H2 / BN, cfg::B / BM);
    gemm_f16<0><<<g2, 256, GEMM_SMEM>>>(
        (const __half*)p_h1, (const __half*)p_W2, (__half*)p_h2,
        nullptr, nullptr, cfg::B, cfg::H2, cfg::H1);
    dim3 g3(cfg::H3 / BN, cfg::B / BM);
    gemm_f16<1><<<g3, 256, GEMM_SMEM>>>(
        (const __half*)p_h2, (const __half*)p_W3, nullptr,
        Wout, out, cfg::B, cfg::H3, cfg::H2);
}

// round 9
// speedup vs baseline: 2.1573x; 1.0922x over previous
#include <cuda_runtime.h>
#include <cuda_bf16.h>
#include <cuda_fp8.h>
#include <cstdint>

// ---------------------------------------------------------------------------
// DeepFM: out = bias + first + second + MLP(emb)
// FP8 e4m3 mma.sync GEMMs, CTA 128x128, BK=128 (fewer barriers), NS=3,
// 256 threads, 2 CTA/SM. K of G1 padded 1728->1792.
// G3 fuses h3 @ Wout into epilogue (atomicAdd into out). FM terms exact fp32.
// Scaling: act/weights fp8 of (value*64); acc = 4096*true.
// ---------------------------------------------------------------------------

namespace cfg {
constexpr int B  = 16384;
constexpr int F  = 26;
constexpr int V  = 100000;
constexpr int D  = 64;
constexpr int ND = 13;
constexpr int H1 = 1024;
constexpr int H2 = 512;
constexpr int H3 = 256;
constexpr int K0 = (F + 1) * D;   // 1728
constexpr int K0P = 1792;         // padded to multiple of 128
}

constexpr float SCALE = 64.f;
constexpr float INV_SCALE = 1.f / 64.f;
constexpr float INV_SCALE2 = 1.f / 4096.f;

// ------------------------- scratch (device globals) ------------------------
__device__ uint8_t g_h  [(size_t)cfg::B * cfg::K0P];  // fp8 e4m3, x64 (padded)
__device__ uint8_t g_h1 [(size_t)cfg::B * cfg::H1];
__device__ uint8_t g_h2 [(size_t)cfg::B * cfg::H2];
__device__ uint8_t g_Wt1[cfg::H1 * cfg::K0P];         // [N,Kpad] fp8, x64
__device__ uint8_t g_Wt2[cfg::H2 * cfg::H1];
__device__ uint8_t g_Wt3[cfg::H3 * cfg::H2];

__device__ __forceinline__ uint8_t to_fp8(float v) {
    return (uint8_t)__nv_cvt_float_to_fp8(v, __NV_SATFINITE, __NV_E4M3);
}

// ------------------------- fused weight transpose+convert ------------------
// z=0: W1[K0,H1]->g_Wt1[H1,K0P] (zero-pad K); z=1: W2->g_Wt2; z=2: W3->g_Wt3
__global__ __launch_bounds__(256) void transpose_convert_all(
    const float* __restrict__ W1, const float* __restrict__ W2,
    const float* __restrict__ W3) {
    const float* in;
    uint8_t* out;
    int K, Kpad, N;
    if (blockIdx.z == 0)      { in = W1; out = g_Wt1; K = cfg::K0; Kpad = cfg::K0P; N = cfg::H1; }
    else if (blockIdx.z == 1) { in = W2; out = g_Wt2; K = cfg::H1; Kpad = cfg::H1;  N = cfg::H2; }
    else                      { in = W3; out = g_Wt3; K = cfg::H2; Kpad = cfg::H2;  N = cfg::H3; }

    const int n0 = blockIdx.x * 32, k0 = blockIdx.y * 32;
    if (n0 >= N || k0 >= Kpad) return;

    __shared__ float t[32][33];
    const int tx = threadIdx.x & 31, ty = threadIdx.x >> 5;  // 32x8
#pragma unroll
    for (int j = 0; j < 4; j++) {
        int k = k0 + ty + j * 8;
        t[ty + j * 8][tx] = (k < K) ? in[(size_t)k * N + n0 + tx] : 0.f;
    }
    __syncthreads();
#pragma unroll
    for (int j = 0; j < 4; j++)
        out[(size_t)(n0 + ty + j * 8) * Kpad + k0 + tx] =
            to_fp8(t[tx][ty + j * 8] * SCALE);
}

// ------------------------- embed + FM (fp32 exact) -------------------------
__global__ __launch_bounds__(256) void embed_kernel(
    const float* __restrict__ dense, const int* __restrict__ sidx,
    const float* __restrict__ bias, const float* __restrict__ emb_tables,
    const float* __restrict__ lin_tables, const float* __restrict__ Wd,
    const float* __restrict__ Wld, const float* __restrict__ bld,
    float* __restrict__ out) {
    const int sub = threadIdx.x >> 6;
    const int d   = threadIdx.x & 63;
    const int row = blockIdx.x * 4 + sub;

    const float* dr = dense + (size_t)row * cfg::ND;

    int idx[cfg::F];
#pragma unroll
    for (int f = 0; f < cfg::F; f++) idx[f] = __ldg(sidx + (size_t)row * cfg::F + f);

    float ev[cfg::F];
#pragma unroll
    for (int f = 0; f < cfg::F; f++)
        ev[f] = __ldg(emb_tables + ((size_t)f * cfg::V + idx[f]) * cfg::D + d);

    float lin = 0.f;
    if (d < cfg::F) lin = __ldg(lin_tables + (size_t)d * cfg::V + idx[d]);

    float de = 0.f;
#pragma unroll
    for (int i = 0; i < cfg::ND; i++) de += dr[i] * Wd[i * cfg::D + d];

    float s  = de;
    float sq = de * de;
    uint8_t* hrow = g_h + (size_t)row * cfg::K0P;
    hrow[d] = to_fp8(de * SCALE);

#pragma unroll
    for (int f = 0; f < cfg::F; f++) {
        float e = ev[f];
        s  += e;
        sq += e * e;
        hrow[(size_t)(f + 1) * cfg::D + d] = to_fp8(e * SCALE);
    }
    hrow[cfg::K0 + d] = 0;   // zero K padding [1728,1792)

    float val = 0.5f * (s * s - sq) + lin;
    if (d < cfg::ND) val += dr[d] * Wld[d];

#pragma unroll
    for (int o = 16; o > 0; o >>= 1)
        val += __shfl_down_sync(0xffffffffu, val, o);

    __shared__ float red[8];
    if ((threadIdx.x & 31) == 0) red[threadIdx.x >> 5] = val;
    __syncthreads();
    if (d == 0)
        out[row] = bias[0] + bld[0] + red[sub * 2] + red[sub * 2 + 1];
}

// ------------------------- FP8 tensor-core GEMM ----------------------------
// CTA 128x128, 8 warps (4M x 2N), warp tile 32x64, BK=128 (4 k32 steps), NS=3.
#define BM 128
#define BN 128
#define BK 128
#define NS 3
#define TSTR 144                    // 128B row + 16B pad (conflict-free)
#define A_ST (BM * TSTR)            // 18432 B / stage
#define B_ST (BN * TSTR)            // 18432 B / stage
#define STAGE_B (A_ST + B_ST)       // 36864
#define GEMM_SMEM (NS * STAGE_B)    // 110592 B

__device__ __forceinline__ uint32_t smem_u32(const void* p) {
    return (uint32_t)__cvta_generic_to_shared(p);
}
__device__ __forceinline__ void cp16(uint32_t s, const void* g) {
    asm volatile("cp.async.cg.shared.global [%0], [%1], 16;\n" ::"r"(s), "l"(g));
}
__device__ __forceinline__ void cp_commit() {
    asm volatile("cp.async.commit_group;\n");
}
template <int N> __device__ __forceinline__ void cp_wait() {
    asm volatile("cp.async.wait_group %0;\n" ::"n"(N));
}
__device__ __forceinline__ void ldm_x4(uint32_t a, uint32_t& r0, uint32_t& r1,
                                       uint32_t& r2, uint32_t& r3) {
    asm volatile("ldmatrix.sync.aligned.m8n8.x4.shared.b16 {%0,%1,%2,%3}, [%4];\n"
                 : "=r"(r0), "=r"(r1), "=r"(r2), "=r"(r3)
                 : "r"(a));
}
__device__ __forceinline__ void mma_fp8(float* c, const uint32_t* a,
                                        uint32_t b0, uint32_t b1) {
    asm volatile(
        "mma.sync.aligned.m16n8k32.row.col.f32.e4m3.e4m3.f32 "
        "{%0,%1,%2,%3}, {%4,%5,%6,%7}, {%8,%9}, {%0,%1,%2,%3};\n"
        : "+f"(c[0]), "+f"(c[1]), "+f"(c[2]), "+f"(c[3])
        : "r"(a[0]), "r"(a[1]), "r"(a[2]), "r"(a[3]), "r"(b0), "r"(b1));
}

// MODE 0: C = fp8(relu(acc)/64).  MODE 1: out[m] += relu(acc)@Wout/4096.
template <int MODE>
__global__ __launch_bounds__(256, 2) void gemm_relu_fp8(
    const uint8_t* __restrict__ A, const uint8_t* __restrict__ Wt,
    uint8_t* __restrict__ C, const float* __restrict__ Wout,
    float* __restrict__ out, int M, int N, int K)
{
    extern __shared__ __align__(16) uint8_t smem[];

    const int tid  = threadIdx.x;
    const int bm   = blockIdx.y * BM;
    const int bn   = blockIdx.x * BN;
    const int wid  = tid >> 5;
    const int lane = tid & 31;
    const int wm   = (wid & 3) * 32;   // 4 warps over M
    const int wn   = (wid >> 2) * 64;  // 2 warps over N

    auto load_tiles = [&](int buf, int kofs) {
        uint8_t* sA = smem + buf * STAGE_B;
        uint8_t* sB = sA + A_ST;
        // A: 128 rows x 8 chunks of 16B (1024 chunks, 4 iters)
#pragma unroll
        for (int it = 0; it < 4; it++) {
            int c = tid + it * 256;
            int r = c >> 3, cg = c & 7;
            cp16(smem_u32(sA + r * TSTR + cg * 16),
                 A + (size_t)(bm + r) * K + kofs + cg * 16);
        }
        // B: 128 n-rows x 8 chunks of 16B (1024 chunks, 4 iters)
#pragma unroll
        for (int it = 0; it < 4; it++) {
            int c = tid + it * 256;
            int r = c >> 3, cg = c & 7;
            cp16(smem_u32(sB + r * TSTR + cg * 16),
                 Wt + (size_t)(bn + r) * K + kofs + cg * 16);
        }
    };

    float acc[2][8][4];
#pragma unroll
    for (int i = 0; i < 2; i++)
#pragma unroll
        for (int j = 0; j < 8; j++)
#pragma unroll
            for (int k = 0; k < 4; k++) acc[i][j][k] = 0.f;

    const int KT = K / BK;

#pragma unroll
    for (int s = 0; s < NS - 1; s++) {
        load_tiles(s, s * BK);
        cp_commit();
    }

    for (int kt = 0; kt < KT; kt++) {
        const int buf = kt % NS;
        cp_wait<NS - 2>();
        __syncthreads();

        const int pf = kt + NS - 1;
        if (pf < KT) load_tiles(pf % NS, pf * BK);
        cp_commit();

        uint8_t* sA = smem + buf * STAGE_B;
        uint8_t* sB = sA + A_ST;
#pragma unroll
        for (int ks = 0; ks < 4; ks++) {         // four k32 steps
            uint32_t af[2][4];
#pragma unroll
            for (int mi = 0; mi < 2; mi++) {
                int r = wm + mi * 16 + (lane & 15);
                int cb = ks * 32 + (lane >> 4) * 16;
                ldm_x4(smem_u32(sA + r * TSTR + cb),
                       af[mi][0], af[mi][1], af[mi][2], af[mi][3]);
            }
            uint32_t bf[4][4];
#pragma unroll
            for (int nj = 0; nj < 4; nj++) {
                int r = wn + nj * 16 + (lane & 15);
                int cb = ks * 32 + (lane >> 4) * 16;
                ldm_x4(smem_u32(sB + r * TSTR + cb),
                       bf[nj][0], bf[nj][1], bf[nj][2], bf[nj][3]);
            }
            // bf regs: r0 n(0-7)k(0-15), r1 n(8-15)k(0-15),
            //          r2 n(0-7)k(16-31), r3 n(8-15)k(16-31)
#pragma unroll
            for (int mi = 0; mi < 2; mi++)
#pragma unroll
                for (int nj = 0; nj < 4; nj++) {
                    mma_fp8(acc[mi][nj * 2],     af[mi], bf[nj][0], bf[nj][2]);
                    mma_fp8(acc[mi][nj * 2 + 1], af[mi], bf[nj][1], bf[nj][3]);
                }
        }
    }

    const int lr = lane >> 2, lc = (lane & 3) * 2;
    if (MODE == 1) {
        // out[m] += relu(acc) @ Wout / 4096
#pragma unroll
        for (int mi = 0; mi < 2; mi++) {
            float s0 = 0.f, s1 = 0.f;
#pragma unroll
            for (int ni = 0; ni < 8; ni++) {
                int n0 = bn + wn + ni * 8 + lc;
                float w0 = __ldg(Wout + n0);
                float w1 = __ldg(Wout + n0 + 1);
                s0 += fmaxf(acc[mi][ni][0], 0.f) * w0 +
                      fmaxf(acc[mi][ni][1], 0.f) * w1;
                s1 += fmaxf(acc[mi][ni][2], 0.f) * w0 +
                      fmaxf(acc[mi][ni][3], 0.f) * w1;
            }
            s0 += __shfl_xor_sync(0xffffffffu, s0, 1);
            s0 += __shfl_xor_sync(0xffffffffu, s0, 2);
            s1 += __shfl_xor_sync(0xffffffffu, s1, 1);
            s1 += __shfl_xor_sync(0xffffffffu, s1, 2);
            if ((lane & 3) == 0) {
                int m0 = bm + wm + mi * 16 + lr;
                atomicAdd(out + m0,     s0 * INV_SCALE2);
                atomicAdd(out + m0 + 8, s1 * INV_SCALE2);
            }
        }
    } else {
#pragma unroll
        for (int mi = 0; mi < 2; mi++)
#pragma unroll
            for (int ni = 0; ni < 8; ni++) {
                int m0 = bm + wm + mi * 16 + lr;
                int n0 = bn + wn + ni * 8 + lc;
                float v0 = fmaxf(acc[mi][ni][0], 0.f) * INV_SCALE;
                float v1 = fmaxf(acc[mi][ni][1], 0.f) * INV_SCALE;
                float v2 = fmaxf(acc[mi][ni][2], 0.f) * INV_SCALE;
                float v3 = fmaxf(acc[mi][ni][3], 0.f) * INV_SCALE;
                *reinterpret_cast<unsigned short*>(C + (size_t)m0 * N + n0) =
                    (unsigned short)__nv_cvt_float2_to_fp8x2(
                        make_float2(v0, v1), __NV_SATFINITE, __NV_E4M3);
                *reinterpret_cast<unsigned short*>(C + (size_t)(m0 + 8) * N + n0) =
                    (unsigned short)__nv_cvt_float2_to_fp8x2(
                        make_float2(v2, v3), __NV_SATFINITE, __NV_E4M3);
            }
    }
}

// ------------------------- launch ------------------------------------------
extern "C" void kernel_launch(void* const* d_in, const int* in_sizes, int n_in,
                              void* d_out, int out_size) {
    const float* dense = (const float*)d_in[0];
    const int*   sidx  = (const int*)d_in[1];
    const float* bias  = (const float*)d_in[2];
    const float* emb   = (const float*)d_in[3];
    const float* lin   = (const float*)d_in[4];
    const float* Wd    = (const float*)d_in[5];
    const float* Wld   = (const float*)d_in[6];
    const float* bld   = (const float*)d_in[7];
    const float* W1    = (const float*)d_in[8];
    const float* W2    = (const float*)d_in[9];
    const float* W3    = (const float*)d_in[10];
    const float* Wout  = (const float*)d_in[11];
    float* out = (float*)d_out;

    void *p_h, *p_h1, *p_h2, *p_W1, *p_W2, *p_W3;
    cudaGetSymbolAddress(&p_h,  g_h);
    cudaGetSymbolAddress(&p_h1, g_h1);
    cudaGetSymbolAddress(&p_h2, g_h2);
    cudaGetSymbolAddress(&p_W1, g_Wt1);
    cudaGetSymbolAddress(&p_W2, g_Wt2);
    cudaGetSymbolAddress(&p_W3, g_Wt3);

    static bool attr_done = false;
    if (!attr_done) {
        cudaFuncSetAttribute(gemm_relu_fp8<0>,
                             cudaFuncAttributeMaxDynamicSharedMemorySize,
                             GEMM_SMEM);
        cudaFuncSetAttribute(gemm_relu_fp8<1>,
                             cudaFuncAttributeMaxDynamicSharedMemorySize,
                             GEMM_SMEM);
        attr_done = true;
    }

    // one fused convert launch (grid covers the largest; small z-slices exit)
    transpose_convert_all<<<dim3(cfg::H1 / 32, cfg::K0P / 32, 3), 256>>>(
        W1, W2, W3);

    embed_kernel<<<cfg::B / 4, 256>>>(dense, sidx, bias, emb, lin, Wd, Wld,
                                      bld, out);

    dim3 g1(cfg::H1 / BN, cfg::B / BM);
    gemm_relu_fp8<0><<<g1, 256, GEMM_SMEM>>>(
        (const uint8_t*)p_h, (const uint8_t*)p_W1, (uint8_t*)p_h1,
        nullptr, nullptr, cfg::B, cfg::H1, cfg::K0P);
    dim3 g2(cfg::H2 / BN, cfg::B / BM);
    gemm_relu_fp8<0><<<g2, 256, GEMM_SMEM>>>(
        (const uint8_t*)p_h1, (const uint8_t*)p_W2, (uint8_t*)p_h2,
        nullptr, nullptr, cfg::B, cfg::H2, cfg::H1);
    dim3 g3(cfg::H3 / BN, cfg::B / BM);
    gemm_relu_fp8<1><<<g3, 256, GEMM_SMEM>>>(
        (const uint8_t*)p_h2, (const uint8_t*)p_W3, nullptr,
        Wout, out, cfg::B, cfg::H3, cfg::H2);
}

// round 10
// speedup vs baseline: 2.2988x; 1.0656x over previous
#include <cuda_runtime.h>
#include <cuda_bf16.h>
#include <cuda_fp8.h>
#include <cstdint>

// ---------------------------------------------------------------------------
// DeepFM: out = bias + first + second + MLP(emb)
// FP8 e4m3 mma.sync GEMMs, CTA 128x128, BK=64, NS=4, 256 thr (R4 champion
// core) + fused weight-convert launch + G3 epilogue fuses h3 @ Wout.
// Per-thread pointer-increment addressing in the mainloop (cut ALU issue).
// Scaling: act/weights fp8 of (value*64); acc = 4096*true. FM terms fp32.
// ---------------------------------------------------------------------------

namespace cfg {
constexpr int B  = 16384;
constexpr int F  = 26;
constexpr int V  = 100000;
constexpr int D  = 64;
constexpr int ND = 13;
constexpr int H1 = 1024;
constexpr int H2 = 512;
constexpr int H3 = 256;
constexpr int K0 = (F + 1) * D;   // 1728
}

constexpr float SCALE = 64.f;
constexpr float INV_SCALE = 1.f / 64.f;
constexpr float INV_SCALE2 = 1.f / 4096.f;

// ------------------------- scratch (device globals) ------------------------
__device__ uint8_t g_h  [(size_t)cfg::B * cfg::K0];   // fp8 e4m3, x64
__device__ uint8_t g_h1 [(size_t)cfg::B * cfg::H1];
__device__ uint8_t g_h2 [(size_t)cfg::B * cfg::H2];
__device__ uint8_t g_Wt1[cfg::H1 * cfg::K0];          // [N,K] fp8, x64
__device__ uint8_t g_Wt2[cfg::H2 * cfg::H1];
__device__ uint8_t g_Wt3[cfg::H3 * cfg::H2];

__device__ __forceinline__ uint8_t to_fp8(float v) {
    return (uint8_t)__nv_cvt_float_to_fp8(v, __NV_SATFINITE, __NV_E4M3);
}

// ------------------------- fused weight transpose+convert ------------------
// z=0: W1->g_Wt1; z=1: W2->g_Wt2; z=2: W3->g_Wt3   (out[n*K+k] = fp8(in*64))
__global__ __launch_bounds__(256) void transpose_convert_all(
    const float* __restrict__ W1, const float* __restrict__ W2,
    const float* __restrict__ W3) {
    const float* in;
    uint8_t* out;
    int K, N;
    if (blockIdx.z == 0)      { in = W1; out = g_Wt1; K = cfg::K0; N = cfg::H1; }
    else if (blockIdx.z == 1) { in = W2; out = g_Wt2; K = cfg::H1; N = cfg::H2; }
    else                      { in = W3; out = g_Wt3; K = cfg::H2; N = cfg::H3; }

    const int n0 = blockIdx.x * 32, k0 = blockIdx.y * 32;
    if (n0 >= N || k0 >= K) return;

    __shared__ float t[32][33];
    const int tx = threadIdx.x & 31, ty = threadIdx.x >> 5;  // 32x8
#pragma unroll
    for (int j = 0; j < 4; j++)
        t[ty + j * 8][tx] = in[(size_t)(k0 + ty + j * 8) * N + n0 + tx];
    __syncthreads();
#pragma unroll
    for (int j = 0; j < 4; j++)
        out[(size_t)(n0 + ty + j * 8) * K + k0 + tx] =
            to_fp8(t[tx][ty + j * 8] * SCALE);
}

// ------------------------- embed + FM (fp32 exact) -------------------------
__global__ __launch_bounds__(256) void embed_kernel(
    const float* __restrict__ dense, const int* __restrict__ sidx,
    const float* __restrict__ bias, const float* __restrict__ emb_tables,
    const float* __restrict__ lin_tables, const float* __restrict__ Wd,
    const float* __restrict__ Wld, const float* __restrict__ bld,
    float* __restrict__ out) {
    const int sub = threadIdx.x >> 6;
    const int d   = threadIdx.x & 63;
    const int row = blockIdx.x * 4 + sub;

    const float* dr = dense + (size_t)row * cfg::ND;

    int idx[cfg::F];
#pragma unroll
    for (int f = 0; f < cfg::F; f++) idx[f] = __ldg(sidx + (size_t)row * cfg::F + f);

    float ev[cfg::F];
#pragma unroll
    for (int f = 0; f < cfg::F; f++)
        ev[f] = __ldg(emb_tables + ((size_t)f * cfg::V + idx[f]) * cfg::D + d);

    float lin = 0.f;
    if (d < cfg::F) lin = __ldg(lin_tables + (size_t)d * cfg::V + idx[d]);

    float de = 0.f;
#pragma unroll
    for (int i = 0; i < cfg::ND; i++) de += dr[i] * Wd[i * cfg::D + d];

    float s  = de;
    float sq = de * de;
    uint8_t* hrow = g_h + (size_t)row * cfg::K0;
    hrow[d] = to_fp8(de * SCALE);

#pragma unroll
    for (int f = 0; f < cfg::F; f++) {
        float e = ev[f];
        s  += e;
        sq += e * e;
        hrow[(size_t)(f + 1) * cfg::D + d] = to_fp8(e * SCALE);
    }

    float val = 0.5f * (s * s - sq) + lin;
    if (d < cfg::ND) val += dr[d] * Wld[d];

#pragma unroll
    for (int o = 16; o > 0; o >>= 1)
        val += __shfl_down_sync(0xffffffffu, val, o);

    __shared__ float red[8];
    if ((threadIdx.x & 31) == 0) red[threadIdx.x >> 5] = val;
    __syncthreads();
    if (d == 0)
        out[row] = bias[0] + bld[0] + red[sub * 2] + red[sub * 2 + 1];
}

// ------------------------- FP8 tensor-core GEMM ----------------------------
// CTA 128x128, 8 warps (4M x 2N), warp tile 32x64, BK=64, NS=4 stages.
#define BM 128
#define BN 128
#define BK 64
#define NS 4
#define TSTR 80                     // 64B row + 16B pad (conflict-free)
#define A_ST (BM * TSTR)            // 10240 B / stage
#define B_ST (BN * TSTR)            // 10240 B / stage
#define STAGE_B (A_ST + B_ST)
#define GEMM_SMEM (NS * STAGE_B)    // 81920 B

__device__ __forceinline__ uint32_t smem_u32(const void* p) {
    return (uint32_t)__cvta_generic_to_shared(p);
}
__device__ __forceinline__ void cp16(uint32_t s, const void* g) {
    asm volatile("cp.async.cg.shared.global [%0], [%1], 16;\n" ::"r"(s), "l"(g));
}
__device__ __forceinline__ void cp_commit() {
    asm volatile("cp.async.commit_group;\n");
}
template <int N> __device__ __forceinline__ void cp_wait() {
    asm volatile("cp.async.wait_group %0;\n" ::"n"(N));
}
__device__ __forceinline__ void ldm_x4(uint32_t a, uint32_t& r0, uint32_t& r1,
                                       uint32_t& r2, uint32_t& r3) {
    asm volatile("ldmatrix.sync.aligned.m8n8.x4.shared.b16 {%0,%1,%2,%3}, [%4];\n"
                 : "=r"(r0), "=r"(r1), "=r"(r2), "=r"(r3)
                 : "r"(a));
}
__device__ __forceinline__ void mma_fp8(float* c, const uint32_t* a,
                                        uint32_t b0, uint32_t b1) {
    asm volatile(
        "mma.sync.aligned.m16n8k32.row.col.f32.e4m3.e4m3.f32 "
        "{%0,%1,%2,%3}, {%4,%5,%6,%7}, {%8,%9}, {%0,%1,%2,%3};\n"
        : "+f"(c[0]), "+f"(c[1]), "+f"(c[2]), "+f"(c[3])
        : "r"(a[0]), "r"(a[1]), "r"(a[2]), "r"(a[3]), "r"(b0), "r"(b1));
}

// MODE 0: C = fp8(relu(acc)/64).  MODE 1: out[m] += relu(acc)@Wout/4096.
template <int MODE>
__global__ __launch_bounds__(256, 2) void gemm_relu_fp8(
    const uint8_t* __restrict__ A, const uint8_t* __restrict__ Wt,
    uint8_t* __restrict__ C, const float* __restrict__ Wout,
    float* __restrict__ out, int M, int N, int K)
{
    extern __shared__ __align__(16) uint8_t smem[];

    const int tid  = threadIdx.x;
    const int bm   = blockIdx.y * BM;
    const int bn   = blockIdx.x * BN;
    const int wid  = tid >> 5;
    const int lane = tid & 31;
    const int wm   = (wid & 3) * 32;   // 4 warps over M
    const int wn   = (wid >> 2) * 64;  // 2 warps over N

    // ---- persistent per-thread load addresses (advance by BK per stage) ----
    const int r0  = tid >> 2;           // 0..63
    const int cg0 = (tid & 3) * 16;     // 0/16/32/48
    const uint8_t* pA = A  + (size_t)(bm + r0) * K + cg0;
    const uint8_t* pB = Wt + (size_t)(bn + r0) * K + cg0;
    const size_t rowstep = (size_t)64 * K;    // +64 rows
    const uint32_t sbase = smem_u32(smem);
    const uint32_t sAoff = sbase + r0 * TSTR + cg0;
    const uint32_t sBoff = sAoff + A_ST;

    auto load_tiles = [&](int buf, const uint8_t* a, const uint8_t* b) {
        const uint32_t so = buf * STAGE_B;
        cp16(sAoff + so,             a);
        cp16(sAoff + so + 64 * TSTR, a + rowstep);
        cp16(sBoff + so,             b);
        cp16(sBoff + so + 64 * TSTR, b + rowstep);
    };

    // ---- per-warp ldmatrix smem bases (buf/mi/ks offsets added in-loop) ----
    const uint32_t aBase = sbase + (wm + (lane & 15)) * TSTR +
                           (lane >> 4) * 16;
    const uint32_t bBase = sbase + A_ST + (wn + (lane & 15)) * TSTR +
                           (lane >> 4) * 16;

    float acc[2][8][4];
#pragma unroll
    for (int i = 0; i < 2; i++)
#pragma unroll
        for (int j = 0; j < 8; j++)
#pragma unroll
            for (int k = 0; k < 4; k++) acc[i][j][k] = 0.f;

    const int KT = K / BK;

#pragma unroll
    for (int s = 0; s < NS - 1; s++) {
        load_tiles(s, pA, pB);
        pA += BK;
        pB += BK;
        cp_commit();
    }

    for (int kt = 0; kt < KT; kt++) {
        const int buf = kt % NS;
        cp_wait<NS - 2>();
        __syncthreads();

        if (kt + NS - 1 < KT) {
            load_tiles((kt + NS - 1) % NS, pA, pB);
            pA += BK;
            pB += BK;
        }
        cp_commit();

        const uint32_t so = buf * STAGE_B;
#pragma unroll
        for (int ks = 0; ks < 2; ks++) {         // two k32 steps
            const uint32_t kso = so + ks * 32;
            uint32_t af[2][4];
#pragma unroll
            for (int mi = 0; mi < 2; mi++)
                ldm_x4(aBase + kso + mi * (16 * TSTR),
                       af[mi][0], af[mi][1], af[mi][2], af[mi][3]);
            uint32_t bf[4][4];
#pragma unroll
            for (int nj = 0; nj < 4; nj++)
                ldm_x4(bBase + kso + nj * (16 * TSTR),
                       bf[nj][0], bf[nj][1], bf[nj][2], bf[nj][3]);
            // bf regs: r0 n(0-7)k(0-15), r1 n(8-15)k(0-15),
            //          r2 n(0-7)k(16-31), r3 n(8-15)k(16-31)
#pragma unroll
            for (int mi = 0; mi < 2; mi++)
#pragma unroll
                for (int nj = 0; nj < 4; nj++) {
                    mma_fp8(acc[mi][nj * 2],     af[mi], bf[nj][0], bf[nj][2]);
                    mma_fp8(acc[mi][nj * 2 + 1], af[mi], bf[nj][1], bf[nj][3]);
                }
        }
    }

    const int lr = lane >> 2, lc = (lane & 3) * 2;
    if (MODE == 1) {
        // out[m] += relu(acc) @ Wout / 4096
#pragma unroll
        for (int mi = 0; mi < 2; mi++) {
            float s0 = 0.f, s1 = 0.f;
#pragma unroll
            for (int ni = 0; ni < 8; ni++) {
                int n0 = bn + wn + ni * 8 + lc;
                float w0 = __ldg(Wout + n0);
                float w1 = __ldg(Wout + n0 + 1);
                s0 += fmaxf(acc[mi][ni][0], 0.f) * w0 +
                      fmaxf(acc[mi][ni][1], 0.f) * w1;
                s1 += fmaxf(acc[mi][ni][2], 0.f) * w0 +
                      fmaxf(acc[mi][ni][3], 0.f) * w1;
            }
            s0 += __shfl_xor_sync(0xffffffffu, s0, 1);
            s0 += __shfl_xor_sync(0xffffffffu, s0, 2);
            s1 += __shfl_xor_sync(0xffffffffu, s1, 1);
            s1 += __shfl_xor_sync(0xffffffffu, s1, 2);
            if ((lane & 3) == 0) {
                int m0 = bm + wm + mi * 16 + lr;
                atomicAdd(out + m0,     s0 * INV_SCALE2);
                atomicAdd(out + m0 + 8, s1 * INV_SCALE2);
            }
        }
    } else {
#pragma unroll
        for (int mi = 0; mi < 2; mi++)
#pragma unroll
            for (int ni = 0; ni < 8; ni++) {
                int m0 = bm + wm + mi * 16 + lr;
                int n0 = bn + wn + ni * 8 + lc;
                float v0 = fmaxf(acc[mi][ni][0], 0.f) * INV_SCALE;
                float v1 = fmaxf(acc[mi][ni][1], 0.f) * INV_SCALE;
                float v2 = fmaxf(acc[mi][ni][2], 0.f) * INV_SCALE;
                float v3 = fmaxf(acc[mi][ni][3], 0.f) * INV_SCALE;
                *reinterpret_cast<unsigned short*>(C + (size_t)m0 * N + n0) =
                    (unsigned short)__nv_cvt_float2_to_fp8x2(
                        make_float2(v0, v1), __NV_SATFINITE, __NV_E4M3);
                *reinterpret_cast<unsigned short*>(C + (size_t)(m0 + 8) * N + n0) =
                    (unsigned short)__nv_cvt_float2_to_fp8x2(
                        make_float2(v2, v3), __NV_SATFINITE, __NV_E4M3);
            }
    }
}

// ------------------------- launch ------------------------------------------
extern "C" void kernel_launch(void* const* d_in, const int* in_sizes, int n_in,
                              void* d_out, int out_size) {
    const float* dense = (const float*)d_in[0];
    const int*   sidx  = (const int*)d_in[1];
    const float* bias  = (const float*)d_in[2];
    const float* emb   = (const float*)d_in[3];
    const float* lin   = (const float*)d_in[4];
    const float* Wd    = (const float*)d_in[5];
    const float* Wld   = (const float*)d_in[6];
    const float* bld   = (const float*)d_in[7];
    const float* W1    = (const float*)d_in[8];
    const float* W2    = (const float*)d_in[9];
    const float* W3    = (const float*)d_in[10];
    const float* Wout  = (const float*)d_in[11];
    float* out = (float*)d_out;

    void *p_h, *p_h1, *p_h2, *p_W1, *p_W2, *p_W3;
    cudaGetSymbolAddress(&p_h,  g_h);
    cudaGetSymbolAddress(&p_h1, g_h1);
    cudaGetSymbolAddress(&p_h2, g_h2);
    cudaGetSymbolAddress(&p_W1, g_Wt1);
    cudaGetSymbolAddress(&p_W2, g_Wt2);
    cudaGetSymbolAddress(&p_W3, g_Wt3);

    static bool attr_done = false;
    if (!attr_done) {
        cudaFuncSetAttribute(gemm_relu_fp8<0>,
                             cudaFuncAttributeMaxDynamicSharedMemorySize,
                             GEMM_SMEM);
        cudaFuncSetAttribute(gemm_relu_fp8<1>,
                             cudaFuncAttributeMaxDynamicSharedMemorySize,
                             GEMM_SMEM);
        attr_done = true;
    }

    // one fused convert launch (largest grid; out-of-range z-slices exit)
    transpose_convert_all<<<dim3(cfg::H1 / 32, cfg::K0 / 32, 3), 256>>>(
        W1, W2, W3);

    embed_kernel<<<cfg::B / 4, 256>>>(dense, sidx, bias, emb, lin, Wd, Wld,
                                      bld, out);

    dim3 g1(cfg::H1 / BN, cfg::B / BM);
    gemm_relu_fp8<0><<<g1, 256, GEMM_SMEM>>>(
        (const uint8_t*)p_h, (const uint8_t*)p_W1, (uint8_t*)p_h1,
        nullptr, nullptr, cfg::B, cfg::H1, cfg::K0);
    dim3 g2(cfg::H2 / BN, cfg::B / BM);
    gemm_relu_fp8<0><<<g2, 256, GEMM_SMEM>>>(
        (const uint8_t*)p_h1, (const uint8_t*)p_W2, (uint8_t*)p_h2,
        nullptr, nullptr, cfg::B, cfg::H2, cfg::H1);
    dim3 g3(cfg::H3 / BN, cfg::B / BM);
    gemm_relu_fp8<1><<<g3, 256, GEMM_SMEM>>>(
        (const uint8_t*)p_h2, (const uint8_t*)p_W3, nullptr,
        Wout, out, cfg::B, cfg::H3, cfg::H2);
}

// round 11
// speedup vs baseline: 2.3443x; 1.0198x over previous
#include <cuda_runtime.h>
#include <cuda_bf16.h>
#include <cuda_fp8.h>
#include <cstdint>

// ---------------------------------------------------------------------------
// DeepFM: out = bias + first + second + MLP(emb)
// FP8 e4m3 mma.sync GEMMs, CTA 128x128, BK=64, NS=4, 256 thr, 2 CTA/SM.
// R11: kt-body loads ALL fragments (both k32 steps, 12 ldmatrix) before the
// 32 mma, breaking the per-step load->use serialization.
// Fused weight-convert launch; G3 epilogue fuses h3 @ Wout.
// Scaling: act/weights fp8 of (value*64); acc = 4096*true. FM terms fp32.
// ---------------------------------------------------------------------------

namespace cfg {
constexpr int B  = 16384;
constexpr int F  = 26;
constexpr int V  = 100000;
constexpr int D  = 64;
constexpr int ND = 13;
constexpr int H1 = 1024;
constexpr int H2 = 512;
constexpr int H3 = 256;
constexpr int K0 = (F + 1) * D;   // 1728
}

constexpr float SCALE = 64.f;
constexpr float INV_SCALE = 1.f / 64.f;
constexpr float INV_SCALE2 = 1.f / 4096.f;

// ------------------------- scratch (device globals) ------------------------
__device__ uint8_t g_h  [(size_t)cfg::B * cfg::K0];   // fp8 e4m3, x64
__device__ uint8_t g_h1 [(size_t)cfg::B * cfg::H1];
__device__ uint8_t g_h2 [(size_t)cfg::B * cfg::H2];
__device__ uint8_t g_Wt1[cfg::H1 * cfg::K0];          // [N,K] fp8, x64
__device__ uint8_t g_Wt2[cfg::H2 * cfg::H1];
__device__ uint8_t g_Wt3[cfg::H3 * cfg::H2];

__device__ __forceinline__ uint8_t to_fp8(float v) {
    return (uint8_t)__nv_cvt_float_to_fp8(v, __NV_SATFINITE, __NV_E4M3);
}

// ------------------------- fused weight transpose+convert ------------------
// z=0: W1->g_Wt1; z=1: W2->g_Wt2; z=2: W3->g_Wt3   (out[n*K+k] = fp8(in*64))
__global__ __launch_bounds__(256) void transpose_convert_all(
    const float* __restrict__ W1, const float* __restrict__ W2,
    const float* __restrict__ W3) {
    const float* in;
    uint8_t* out;
    int K, N;
    if (blockIdx.z == 0)      { in = W1; out = g_Wt1; K = cfg::K0; N = cfg::H1; }
    else if (blockIdx.z == 1) { in = W2; out = g_Wt2; K = cfg::H1; N = cfg::H2; }
    else                      { in = W3; out = g_Wt3; K = cfg::H2; N = cfg::H3; }

    const int n0 = blockIdx.x * 32, k0 = blockIdx.y * 32;
    if (n0 >= N || k0 >= K) return;

    __shared__ float t[32][33];
    const int tx = threadIdx.x & 31, ty = threadIdx.x >> 5;  // 32x8
#pragma unroll
    for (int j = 0; j < 4; j++)
        t[ty + j * 8][tx] = in[(size_t)(k0 + ty + j * 8) * N + n0 + tx];
    __syncthreads();
#pragma unroll
    for (int j = 0; j < 4; j++)
        out[(size_t)(n0 + ty + j * 8) * K + k0 + tx] =
            to_fp8(t[tx][ty + j * 8] * SCALE);
}

// ------------------------- embed + FM (fp32 exact) -------------------------
__global__ __launch_bounds__(256) void embed_kernel(
    const float* __restrict__ dense, const int* __restrict__ sidx,
    const float* __restrict__ bias, const float* __restrict__ emb_tables,
    const float* __restrict__ lin_tables, const float* __restrict__ Wd,
    const float* __restrict__ Wld, const float* __restrict__ bld,
    float* __restrict__ out) {
    const int sub = threadIdx.x >> 6;
    const int d   = threadIdx.x & 63;
    const int row = blockIdx.x * 4 + sub;

    const float* dr = dense + (size_t)row * cfg::ND;

    int idx[cfg::F];
#pragma unroll
    for (int f = 0; f < cfg::F; f++) idx[f] = __ldg(sidx + (size_t)row * cfg::F + f);

    float ev[cfg::F];
#pragma unroll
    for (int f = 0; f < cfg::F; f++)
        ev[f] = __ldg(emb_tables + ((size_t)f * cfg::V + idx[f]) * cfg::D + d);

    float lin = 0.f;
    if (d < cfg::F) lin = __ldg(lin_tables + (size_t)d * cfg::V + idx[d]);

    float de = 0.f;
#pragma unroll
    for (int i = 0; i < cfg::ND; i++) de += dr[i] * Wd[i * cfg::D + d];

    float s  = de;
    float sq = de * de;
    uint8_t* hrow = g_h + (size_t)row * cfg::K0;
    hrow[d] = to_fp8(de * SCALE);

#pragma unroll
    for (int f = 0; f < cfg::F; f++) {
        float e = ev[f];
        s  += e;
        sq += e * e;
        hrow[(size_t)(f + 1) * cfg::D + d] = to_fp8(e * SCALE);
    }

    float val = 0.5f * (s * s - sq) + lin;
    if (d < cfg::ND) val += dr[d] * Wld[d];

#pragma unroll
    for (int o = 16; o > 0; o >>= 1)
        val += __shfl_down_sync(0xffffffffu, val, o);

    __shared__ float red[8];
    if ((threadIdx.x & 31) == 0) red[threadIdx.x >> 5] = val;
    __syncthreads();
    if (d == 0)
        out[row] = bias[0] + bld[0] + red[sub * 2] + red[sub * 2 + 1];
}

// ------------------------- FP8 tensor-core GEMM ----------------------------
// CTA 128x128, 8 warps (4M x 2N), warp tile 32x64, BK=64, NS=4 stages.
#define BM 128
#define BN 128
#define BK 64
#define NS 4
#define TSTR 80                     // 64B row + 16B pad (conflict-free)
#define A_ST (BM * TSTR)            // 10240 B / stage
#define B_ST (BN * TSTR)            // 10240 B / stage
#define STAGE_B (A_ST + B_ST)
#define GEMM_SMEM (NS * STAGE_B)    // 81920 B

__device__ __forceinline__ uint32_t smem_u32(const void* p) {
    return (uint32_t)__cvta_generic_to_shared(p);
}
__device__ __forceinline__ void cp16(uint32_t s, const void* g) {
    asm volatile("cp.async.cg.shared.global [%0], [%1], 16;\n" ::"r"(s), "l"(g));
}
__device__ __forceinline__ void cp_commit() {
    asm volatile("cp.async.commit_group;\n");
}
template <int N> __device__ __forceinline__ void cp_wait() {
    asm volatile("cp.async.wait_group %0;\n" ::"n"(N));
}
__device__ __forceinline__ void ldm_x4(uint32_t a, uint32_t& r0, uint32_t& r1,
                                       uint32_t& r2, uint32_t& r3) {
    asm volatile("ldmatrix.sync.aligned.m8n8.x4.shared.b16 {%0,%1,%2,%3}, [%4];\n"
                 : "=r"(r0), "=r"(r1), "=r"(r2), "=r"(r3)
                 : "r"(a));
}
__device__ __forceinline__ void mma_fp8(float* c, const uint32_t* a,
                                        uint32_t b0, uint32_t b1) {
    asm volatile(
        "mma.sync.aligned.m16n8k32.row.col.f32.e4m3.e4m3.f32 "
        "{%0,%1,%2,%3}, {%4,%5,%6,%7}, {%8,%9}, {%0,%1,%2,%3};\n"
        : "+f"(c[0]), "+f"(c[1]), "+f"(c[2]), "+f"(c[3])
        : "r"(a[0]), "r"(a[1]), "r"(a[2]), "r"(a[3]), "r"(b0), "r"(b1));
}

// MODE 0: C = fp8(relu(acc)/64).  MODE 1: out[m] += relu(acc)@Wout/4096.
template <int MODE>
__global__ __launch_bounds__(256, 2) void gemm_relu_fp8(
    const uint8_t* __restrict__ A, const uint8_t* __restrict__ Wt,
    uint8_t* __restrict__ C, const float* __restrict__ Wout,
    float* __restrict__ out, int M, int N, int K)
{
    extern __shared__ __align__(16) uint8_t smem[];

    const int tid  = threadIdx.x;
    const int bm   = blockIdx.y * BM;
    const int bn   = blockIdx.x * BN;
    const int wid  = tid >> 5;
    const int lane = tid & 31;
    const int wm   = (wid & 3) * 32;   // 4 warps over M
    const int wn   = (wid >> 2) * 64;  // 2 warps over N

    // ---- persistent per-thread load addresses (advance by BK per stage) ----
    const int r0  = tid >> 2;           // 0..63
    const int cg0 = (tid & 3) * 16;     // 0/16/32/48
    const uint8_t* pA = A  + (size_t)(bm + r0) * K + cg0;
    const uint8_t* pB = Wt + (size_t)(bn + r0) * K + cg0;
    const size_t rowstep = (size_t)64 * K;    // +64 rows
    const uint32_t sbase = smem_u32(smem);
    const uint32_t sAoff = sbase + r0 * TSTR + cg0;
    const uint32_t sBoff = sAoff + A_ST;

    auto load_tiles = [&](int buf, const uint8_t* a, const uint8_t* b) {
        const uint32_t so = buf * STAGE_B;
        cp16(sAoff + so,             a);
        cp16(sAoff + so + 64 * TSTR, a + rowstep);
        cp16(sBoff + so,             b);
        cp16(sBoff + so + 64 * TSTR, b + rowstep);
    };

    // ---- per-warp ldmatrix smem bases ----
    const uint32_t aBase = sbase + (wm + (lane & 15)) * TSTR +
                           (lane >> 4) * 16;
    const uint32_t bBase = sbase + A_ST + (wn + (lane & 15)) * TSTR +
                           (lane >> 4) * 16;

    float acc[2][8][4];
#pragma unroll
    for (int i = 0; i < 2; i++)
#pragma unroll
        for (int j = 0; j < 8; j++)
#pragma unroll
            for (int k = 0; k < 4; k++) acc[i][j][k] = 0.f;

    const int KT = K / BK;

#pragma unroll
    for (int s = 0; s < NS - 1; s++) {
        load_tiles(s, pA, pB);
        pA += BK;
        pB += BK;
        cp_commit();
    }

    for (int kt = 0; kt < KT; kt++) {
        const int buf = kt % NS;
        cp_wait<NS - 2>();
        __syncthreads();

        if (kt + NS - 1 < KT) {
            load_tiles((kt + NS - 1) % NS, pA, pB);
            pA += BK;
            pB += BK;
        }
        cp_commit();

        const uint32_t so = buf * STAGE_B;

        // ---- issue ALL fragment loads for both k32 steps first ----
        uint32_t af[2][2][4], bf[2][4][4];
#pragma unroll
        for (int ks = 0; ks < 2; ks++) {
            const uint32_t kso = so + ks * 32;
#pragma unroll
            for (int mi = 0; mi < 2; mi++)
                ldm_x4(aBase + kso + mi * (16 * TSTR),
                       af[ks][mi][0], af[ks][mi][1],
                       af[ks][mi][2], af[ks][mi][3]);
#pragma unroll
            for (int nj = 0; nj < 4; nj++)
                ldm_x4(bBase + kso + nj * (16 * TSTR),
                       bf[ks][nj][0], bf[ks][nj][1],
                       bf[ks][nj][2], bf[ks][nj][3]);
        }
        // ---- then all 32 mma ----
#pragma unroll
        for (int ks = 0; ks < 2; ks++)
#pragma unroll
            for (int mi = 0; mi < 2; mi++)
#pragma unroll
                for (int nj = 0; nj < 4; nj++) {
                    mma_fp8(acc[mi][nj * 2],     af[ks][mi],
                            bf[ks][nj][0], bf[ks][nj][2]);
                    mma_fp8(acc[mi][nj * 2 + 1], af[ks][mi],
                            bf[ks][nj][1], bf[ks][nj][3]);
                }
    }

    const int lr = lane >> 2, lc = (lane & 3) * 2;
    if (MODE == 1) {
        // out[m] += relu(acc) @ Wout / 4096
#pragma unroll
        for (int mi = 0; mi < 2; mi++) {
            float s0 = 0.f, s1 = 0.f;
#pragma unroll
            for (int ni = 0; ni < 8; ni++) {
                int n0 = bn + wn + ni * 8 + lc;
                float w0 = __ldg(Wout + n0);
                float w1 = __ldg(Wout + n0 + 1);
                s0 += fmaxf(acc[mi][ni][0], 0.f) * w0 +
                      fmaxf(acc[mi][ni][1], 0.f) * w1;
                s1 += fmaxf(acc[mi][ni][2], 0.f) * w0 +
                      fmaxf(acc[mi][ni][3], 0.f) * w1;
            }
            s0 += __shfl_xor_sync(0xffffffffu, s0, 1);
            s0 += __shfl_xor_sync(0xffffffffu, s0, 2);
            s1 += __shfl_xor_sync(0xffffffffu, s1, 1);
            s1 += __shfl_xor_sync(0xffffffffu, s1, 2);
            if ((lane & 3) == 0) {
                int m0 = bm + wm + mi * 16 + lr;
                atomicAdd(out + m0,     s0 * INV_SCALE2);
                atomicAdd(out + m0 + 8, s1 * INV_SCALE2);
            }
        }
    } else {
#pragma unroll
        for (int mi = 0; mi < 2; mi++)
#pragma unroll
            for (int ni = 0; ni < 8; ni++) {
                int m0 = bm + wm + mi * 16 + lr;
                int n0 = bn + wn + ni * 8 + lc;
                float v0 = fmaxf(acc[mi][ni][0], 0.f) * INV_SCALE;
                float v1 = fmaxf(acc[mi][ni][1], 0.f) * INV_SCALE;
                float v2 = fmaxf(acc[mi][ni][2], 0.f) * INV_SCALE;
                float v3 = fmaxf(acc[mi][ni][3], 0.f) * INV_SCALE;
                *reinterpret_cast<unsigned short*>(C + (size_t)m0 * N + n0) =
                    (unsigned short)__nv_cvt_float2_to_fp8x2(
                        make_float2(v0, v1), __NV_SATFINITE, __NV_E4M3);
                *reinterpret_cast<unsigned short*>(C + (size_t)(m0 + 8) * N + n0) =
                    (unsigned short)__nv_cvt_float2_to_fp8x2(
                        make_float2(v2, v3), __NV_SATFINITE, __NV_E4M3);
            }
    }
}

// ------------------------- launch ------------------------------------------
extern "C" void kernel_launch(void* const* d_in, const int* in_sizes, int n_in,
                              void* d_out, int out_size) {
    const float* dense = (const float*)d_in[0];
    const int*   sidx  = (const int*)d_in[1];
    const float* bias  = (const float*)d_in[2];
    const float* emb   = (const float*)d_in[3];
    const float* lin   = (const float*)d_in[4];
    const float* Wd    = (const float*)d_in[5];
    const float* Wld   = (const float*)d_in[6];
    const float* bld   = (const float*)d_in[7];
    const float* W1    = (const float*)d_in[8];
    const float* W2    = (const float*)d_in[9];
    const float* W3    = (const float*)d_in[10];
    const float* Wout  = (const float*)d_in[11];
    float* out = (float*)d_out;

    void *p_h, *p_h1, *p_h2, *p_W1, *p_W2, *p_W3;
    cudaGetSymbolAddress(&p_h,  g_h);
    cudaGetSymbolAddress(&p_h1, g_h1);
    cudaGetSymbolAddress(&p_h2, g_h2);
    cudaGetSymbolAddress(&p_W1, g_Wt1);
    cudaGetSymbolAddress(&p_W2, g_Wt2);
    cudaGetSymbolAddress(&p_W3, g_Wt3);

    static bool attr_done = false;
    if (!attr_done) {
        cudaFuncSetAttribute(gemm_relu_fp8<0>,
                             cudaFuncAttributeMaxDynamicSharedMemorySize,
                             GEMM_SMEM);
        cudaFuncSetAttribute(gemm_relu_fp8<1>,
                             cudaFuncAttributeMaxDynamicSharedMemorySize,
                             GEMM_SMEM);
        attr_done = true;
    }

    transpose_convert_all<<<dim3(cfg::H1 / 32, cfg::K0 / 32, 3), 256>>>(
        W1, W2, W3);

    embed_kernel<<<cfg::B / 4, 256>>>(dense, sidx, bias, emb, lin, Wd, Wld,
                                      bld, out);

    dim3 g1(cfg::H1 / BN, cfg::B / BM);
    gemm_relu_fp8<0><<<g1, 256, GEMM_SMEM>>>(
        (const uint8_t*)p_h, (const uint8_t*)p_W1, (uint8_t*)p_h1,
        nullptr, nullptr, cfg::B, cfg::H1, cfg::K0);
    dim3 g2(cfg::H2 / BN, cfg::B / BM);
    gemm_relu_fp8<0><<<g2, 256, GEMM_SMEM>>>(
        (const uint8_t*)p_h1, (const uint8_t*)p_W2, (uint8_t*)p_h2,
        nullptr, nullptr, cfg::B, cfg::H2, cfg::H1);
    dim3 g3(cfg::H3 / BN, cfg::B / BM);
    gemm_relu_fp8<1><<<g3, 256, GEMM_SMEM>>>(
        (const uint8_t*)p_h2, (const uint8_t*)p_W3, nullptr,
        Wout, out, cfg::B, cfg::H3, cfg::H2);
}